// round 8
// baseline (speedup 1.0000x reference)
#include <cuda_runtime.h>
#include <math.h>

#define H 1024
#define V 50257
#define L 4096
#define NPART 512                   // fused-attn blocks (8 enc rows each)
#define NRED 64                     // reducer blocks inside fused kernel
#define NB2 444                     // persistent logits blocks (3/SM x 148)
#define NT 3142                     // row tiles of 16 for the big matvec
#define NEG_BIG (-3.0e38f)

// ---------------- device scratch (no allocations allowed) ----------------
__device__ float g_concat[2 * H];            // [0..H) = ctx, [H..2H) = h_new
__device__ float4 g_ctx_part4[NPART * 256];  // 512 partials x 1024 cols (float4) = 2 MB
__device__ float g_spart[2 * NPART];         // per-block (max, sumexp) for attn softmax
__device__ float g_part[2 * NB2];            // per-block (max, sumexp) for logit LSE
__device__ int g_syncA, g_syncB, g_syncC;    // fused kernel phases
__device__ int g_syncD;                      // persistent logits grid sync

// ---------------- helpers ----------------
__device__ __forceinline__ float warp_sum(float v) {
#pragma unroll
    for (int o = 16; o > 0; o >>= 1) v += __shfl_down_sync(0xFFFFFFFFu, v, o);
    return v;
}
__device__ __forceinline__ float dot4(const float4 a, const float4 b) {
    return a.x * b.x + a.y * b.y + a.z * b.z + a.w * b.w;
}
__device__ __forceinline__ void spin_until(volatile int* c, int n) {
    while (*c < n) { }
}

// ============ 1) FUSED: GRU (2 outputs/block) -> scores -> softmax -> ctx ============
__global__ void __launch_bounds__(256, 4) fused_attn_kernel(
    const int* __restrict__ inp, const float* __restrict__ hidden,
    const float* __restrict__ embedding,
    const float* __restrict__ w_ih, const float* __restrict__ w_hh,
    const float* __restrict__ b_ih, const float* __restrict__ b_hh,
    const float* __restrict__ enc, float* __restrict__ out_h)
{
    __shared__ float4 sv[H / 4];      // phase0: x(emb); phase1: h_new
    __shared__ float4 hv4[H / 4];     // phase0: hidden
    __shared__ float red[12][8];
    __shared__ float sarr[8];
    __shared__ float wts[8];
    const int tid = threadIdx.x;
    const int warp = tid >> 5, lane = tid & 31;
    const int b = blockIdx.x;

    if (b == 0 && tid == 0) g_syncD = 0;      // reset kernel-2 counter for this replay

    // ---------------- phase 0: GRU, outputs j0 and j0+1 ----------------
    const int idx = inp[0];
    const int j0 = b * 2;
    const float4* emb4 = (const float4*)(embedding + (size_t)idx * H);
    const float4* hid4 = (const float4*)hidden;
    sv[tid]  = emb4[tid];
    hv4[tid] = hid4[tid];
    __syncthreads();
    const float4 xv = sv[tid];
    const float4 hv = hv4[tid];
    const float4* wi = (const float4*)w_ih;
    const float4* wh = (const float4*)w_hh;
    float a[12];
#pragma unroll
    for (int jj = 0; jj < 2; jj++) {
        const int j = j0 + jj;
#pragma unroll
        for (int g = 0; g < 3; g++) {
            a[jj * 6 + g]     = dot4(wi[(size_t)(j + g * H) * 256 + tid], xv);
            a[jj * 6 + 3 + g] = dot4(wh[(size_t)(j + g * H) * 256 + tid], hv);
        }
    }
#pragma unroll
    for (int q = 0; q < 12; q++) {
        a[q] = warp_sum(a[q]);
        if (lane == 0) red[q][warp] = a[q];
    }
    __syncthreads();
    if (tid < 2) {
        const int j = j0 + tid;
        float s[6];
#pragma unroll
        for (int g = 0; g < 6; g++) {
            float t = red[tid * 6 + g][0];
#pragma unroll
            for (int k = 1; k < 8; k++) t += red[tid * 6 + g][k];
            s[g] = t;
        }
        const float i_r = s[0] + b_ih[j];
        const float i_z = s[1] + b_ih[j + H];
        const float i_n = s[2] + b_ih[j + 2 * H];
        const float h_r = s[3] + b_hh[j];
        const float h_z = s[4] + b_hh[j + H];
        const float h_n = s[5] + b_hh[j + 2 * H];
        const float r = 1.f / (1.f + __expf(-(i_r + h_r)));
        const float z = 1.f / (1.f + __expf(-(i_z + h_z)));
        const float n = tanhf(i_n + r * h_n);
        const float hj = ((const float*)hv4)[j & (H - 1)] ;  // hidden[j]; j<H so mask is identity
        const float val = (1.f - z) * n + z * hj;
        g_concat[H + j] = val;
        out_h[j]        = val;
    }
    __threadfence();
    __syncthreads();
    if (tid == 0) { atomicAdd(&g_syncA, 1); spin_until(&g_syncA, NPART); }
    __syncthreads();
    __threadfence();

    // ---------------- phase 1: scores for rows l0..l0+7, enc held in registers -------
    sv[tid] = ((const float4*)g_concat)[256 + tid];   // h_new
    __syncthreads();
    const float4 hsh = sv[tid];
    const int l0 = b * 8;
    const float4* e4 = (const float4*)enc;
    float4 rv[8];
    float p[8];
#pragma unroll
    for (int l = 0; l < 8; l++) {
        rv[l] = e4[(size_t)(l0 + l) * 256 + tid];
        p[l] = dot4(rv[l], hsh);
    }
#pragma unroll
    for (int l = 0; l < 8; l++) {
        p[l] = warp_sum(p[l]);
        if (lane == 0) red[l][warp] = p[l];
    }
    __syncthreads();
    if (tid < 8) {
        float t = red[tid][0];
#pragma unroll
        for (int k = 1; k < 8; k++) t += red[tid][k];
        sarr[tid] = t;
    }
    __syncthreads();
    if (tid == 0) {
        float m = sarr[0];
#pragma unroll
        for (int k = 1; k < 8; k++) m = fmaxf(m, sarr[k]);
        float s = 0.f;
#pragma unroll
        for (int k = 0; k < 8; k++) s += __expf(sarr[k] - m);
        g_spart[2 * b]     = m;
        g_spart[2 * b + 1] = s;
    }
    __threadfence();
    __syncthreads();
    if (tid == 0) { atomicAdd(&g_syncB, 1); spin_until(&g_syncB, NPART); }
    __syncthreads();
    __threadfence();

    // ---------------- phase 2: merge softmax partials, weighted ctx from registers ----
    {
        float m = g_spart[2 * tid], s = g_spart[2 * tid + 1];
        const float m2 = g_spart[2 * (tid + 256)], s2 = g_spart[2 * (tid + 256) + 1];
        const float nm0 = fmaxf(m, m2);
        s = s * __expf(m - nm0) + s2 * __expf(m2 - nm0);
        m = nm0;
#pragma unroll
        for (int o = 16; o > 0; o >>= 1) {
            const float om = __shfl_down_sync(0xFFFFFFFFu, m, o);
            const float os = __shfl_down_sync(0xFFFFFFFFu, s, o);
            const float nm = fmaxf(m, om);
            s = s * __expf(m - nm) + os * __expf(om - nm);
            m = nm;
        }
        if (lane == 0) { red[0][warp] = m; red[1][warp] = s; }
    }
    __syncthreads();
    if (tid < 8) {
        float M = red[0][0], S = red[1][0];
#pragma unroll
        for (int k = 1; k < 8; k++) {
            const float nm = fmaxf(M, red[0][k]);
            S = S * __expf(M - nm) + red[1][k] * __expf(red[0][k] - nm);
            M = nm;
        }
        wts[tid] = __expf(sarr[tid] - M) / S;
    }
    __syncthreads();
    float4 acc = make_float4(0.f, 0.f, 0.f, 0.f);
#pragma unroll
    for (int l = 0; l < 8; l++) {
        const float w = wts[l];
        acc.x += w * rv[l].x; acc.y += w * rv[l].y;
        acc.z += w * rv[l].z; acc.w += w * rv[l].w;
    }
    g_ctx_part4[b * 256 + tid] = acc;
    __threadfence();
    __syncthreads();
    if (tid == 0) atomicAdd(&g_syncC, 1);

    // ---------------- phase 3: blocks 0..63 reduce the L2-hot partials ----------------
    if (b < NRED) {
        if (tid == 0) spin_until(&g_syncC, NPART);
        __syncthreads();
        __threadfence();
        __shared__ float4 sred[256];
        const int c4 = tid & 3;
        const int pg = tid >> 2;
        float4 racc = make_float4(0.f, 0.f, 0.f, 0.f);
#pragma unroll
        for (int k = 0; k < NPART / 64; k++) {
            const float4 v = g_ctx_part4[(pg + 64 * k) * 256 + b * 4 + c4];
            racc.x += v.x; racc.y += v.y; racc.z += v.z; racc.w += v.w;
        }
        sred[tid] = racc;
        __syncthreads();
#pragma unroll
        for (int off = 32; off >= 1; off >>= 1) {
            if (pg < off) {
                const float4 v = sred[tid + off * 4];
                float4 t = sred[tid];
                t.x += v.x; t.y += v.y; t.z += v.z; t.w += v.w;
                sred[tid] = t;
            }
            __syncthreads();
        }
        if (pg == 0) ((float4*)g_concat)[b * 4 + c4] = sred[tid];
    }
}

// ============ 2) persistent logits matvec + fused LSE + log-softmax ============
__global__ void __launch_bounds__(512, 3) logits_persist_kernel(
    const float* __restrict__ out_w, const float* __restrict__ out_b,
    float* __restrict__ logits)
{
    __shared__ float4 cs[512];
    __shared__ float arr[16];
    __shared__ float sm[16], ss[16];
    __shared__ float bcast;
    const int tid = threadIdx.x;
    const int warp = tid >> 5, lane = tid & 31;

    if (blockIdx.x == 0 && tid == 0) { g_syncA = 0; g_syncB = 0; g_syncC = 0; }  // reset for next replay

    const float4* cc = (const float4*)g_concat;
    cs[tid] = cc[tid];
    __syncthreads();

    float rm = NEG_BIG, rs = 0.f;     // thread 0's running (max, sumexp)
    for (int t = blockIdx.x; t < NT; t += NB2) {
        const int row = t * 16 + warp;
        float lg = NEG_BIG;
        if (row < V) {
            const float4* wr = (const float4*)(out_w + (size_t)row * (2 * H));
            float acc = 0.f;
#pragma unroll
            for (int i = 0; i < 16; i++) {
                const float4 w4 = __ldcs(&wr[lane + 32 * i]);
                const float4 c4 = cs[lane + 32 * i];
                acc += w4.x * c4.x + w4.y * c4.y + w4.z * c4.z + w4.w * c4.w;
            }
            acc = warp_sum(acc);
            if (lane == 0) { lg = acc + out_b[row]; logits[row] = lg; }
        }
        if (lane == 0) arr[warp] = lg;
        __syncthreads();
        if (tid == 0) {
            float m = arr[0];
#pragma unroll
            for (int k = 1; k < 16; k++) m = fmaxf(m, arr[k]);
            const float nm = fmaxf(rm, m);
            float s = 0.f;
#pragma unroll
            for (int k = 0; k < 16; k++) s += __expf(arr[k] - nm);   // NEG_BIG -> 0
            rs = rs * __expf(rm - nm) + s;
            rm = nm;
        }
        __syncthreads();
    }
    if (tid == 0) {
        g_part[2 * blockIdx.x]     = rm;
        g_part[2 * blockIdx.x + 1] = rs;
    }
    __threadfence();
    __syncthreads();
    if (tid == 0) { atomicAdd(&g_syncD, 1); spin_until(&g_syncD, NB2); }
    __syncthreads();
    __threadfence();

    // redundant merge of NB2=444 pairs (fixed order -> deterministic)
    float mm = NEG_BIG, msum = 0.f;
    if (tid < NB2) { mm = g_part[2 * tid]; msum = g_part[2 * tid + 1]; }
#pragma unroll
    for (int o = 16; o > 0; o >>= 1) {
        const float om = __shfl_down_sync(0xFFFFFFFFu, mm, o);
        const float os = __shfl_down_sync(0xFFFFFFFFu, msum, o);
        const float nm = fmaxf(mm, om);
        msum = msum * __expf(mm - nm) + os * __expf(om - nm);
        mm = nm;
    }
    if (lane == 0) { sm[warp] = mm; ss[warp] = msum; }
    __syncthreads();
    if (tid == 0) {
        float M = sm[0], S = ss[0];
#pragma unroll
        for (int k = 1; k < 16; k++) {
            const float nm = fmaxf(M, sm[k]);
            S = S * __expf(M - nm) + ss[k] * __expf(sm[k] - nm);
            M = nm;
        }
        bcast = M + logf(S);
    }
    __syncthreads();
    const float lse = bcast;
    const int v = blockIdx.x * 512 + tid;     // NB2*512 = 227328 >= V: single pass
    if (v < V) logits[v] -= lse;
}

// ---------------- launcher ----------------
extern "C" void kernel_launch(void* const* d_in, const int* in_sizes, int n_in,
                              void* d_out, int out_size)
{
    const int*   inp   = (const int*)  d_in[0];   // token id (read low 32 bits)
    const float* hidden= (const float*)d_in[1];
    const float* enc   = (const float*)d_in[2];
    const float* emb   = (const float*)d_in[3];
    const float* w_ih  = (const float*)d_in[4];
    const float* w_hh  = (const float*)d_in[5];
    const float* b_ih  = (const float*)d_in[6];
    const float* b_hh  = (const float*)d_in[7];
    const float* out_w = (const float*)d_in[8];
    const float* out_b = (const float*)d_in[9];
    float* out = (float*)d_out;                   // [0..V) log-probs, [V..V+H) h_new

    fused_attn_kernel<<<NPART, 256>>>(inp, hidden, emb, w_ih, w_hh, b_ih, b_hh,
                                      enc, out + V);
    logits_persist_kernel<<<NB2, 512>>>(out_w, out_b, out);
}

// round 9
// speedup vs baseline: 1.0734x; 1.0734x over previous
#include <cuda_runtime.h>
#include <math.h>

#define H 1024
#define V 50257
#define L 4096
#define NPART 512                   // fused-attn blocks (8 enc rows each)
#define NRED 64                     // reducer blocks inside fused kernel
#define FIN_BLOCKS ((V + 255) / 256)   // 197
#define NEG_BIG (-3.0e38f)

// ---------------- device scratch (no allocations allowed) ----------------
__device__ float g_concat[2 * H];            // [0..H) = ctx, [H..2H) = h_new
__device__ float4 g_ctx_part4[NPART * 256];  // 512 partials x 1024 cols (float4) = 2 MB
__device__ float g_spart[2 * NPART];         // per-block (max, sumexp) for attn softmax
__device__ float g_part[2 * FIN_BLOCKS];     // per-block (max, sumexp) for logit LSE
__device__ int g_syncA, g_syncB, g_syncC;    // fused kernel phases
__device__ int g_lse_done;                   // finalize grid sync

// ---------------- helpers ----------------
__device__ __forceinline__ float warp_sum(float v) {
#pragma unroll
    for (int o = 16; o > 0; o >>= 1) v += __shfl_down_sync(0xFFFFFFFFu, v, o);
    return v;
}
__device__ __forceinline__ float dot4(const float4 a, const float4 b) {
    return a.x * b.x + a.y * b.y + a.z * b.z + a.w * b.w;
}
__device__ __forceinline__ void spin_until(volatile int* c, int n) {
    while (*c < n) { }
}

// ============ 1) FUSED: GRU (2 outputs/block) -> scores -> softmax -> ctx ============
__global__ void __launch_bounds__(256, 4) fused_attn_kernel(
    const int* __restrict__ inp, const float* __restrict__ hidden,
    const float* __restrict__ embedding,
    const float* __restrict__ w_ih, const float* __restrict__ w_hh,
    const float* __restrict__ b_ih, const float* __restrict__ b_hh,
    const float* __restrict__ enc, float* __restrict__ out_h)
{
    __shared__ float4 sv[H / 4];      // phase0: x(emb); phase1: h_new
    __shared__ float4 hv4[H / 4];     // phase0: hidden
    __shared__ float red[12][8];
    __shared__ float sarr[8];
    __shared__ float wts[8];
    const int tid = threadIdx.x;
    const int warp = tid >> 5, lane = tid & 31;
    const int b = blockIdx.x;

    if (b == 0 && tid == 0) g_lse_done = 0;   // reset finalize counter for this replay

    // ---------------- phase 0: GRU, outputs j0 and j0+1 ----------------
    const int idx = inp[0];
    const int j0 = b * 2;
    const float4* emb4 = (const float4*)(embedding + (size_t)idx * H);
    const float4* hid4 = (const float4*)hidden;
    sv[tid]  = emb4[tid];
    hv4[tid] = hid4[tid];
    __syncthreads();
    const float4 xv = sv[tid];
    const float4 hv = hv4[tid];
    const float4* wi = (const float4*)w_ih;
    const float4* wh = (const float4*)w_hh;
    float a[12];
#pragma unroll
    for (int jj = 0; jj < 2; jj++) {
        const int j = j0 + jj;
#pragma unroll
        for (int g = 0; g < 3; g++) {
            a[jj * 6 + g]     = dot4(wi[(size_t)(j + g * H) * 256 + tid], xv);
            a[jj * 6 + 3 + g] = dot4(wh[(size_t)(j + g * H) * 256 + tid], hv);
        }
    }
#pragma unroll
    for (int q = 0; q < 12; q++) {
        a[q] = warp_sum(a[q]);
        if (lane == 0) red[q][warp] = a[q];
    }
    __syncthreads();
    if (tid < 2) {
        const int j = j0 + tid;
        float s[6];
#pragma unroll
        for (int g = 0; g < 6; g++) {
            float t = red[tid * 6 + g][0];
#pragma unroll
            for (int k = 1; k < 8; k++) t += red[tid * 6 + g][k];
            s[g] = t;
        }
        const float i_r = s[0] + b_ih[j];
        const float i_z = s[1] + b_ih[j + H];
        const float i_n = s[2] + b_ih[j + 2 * H];
        const float h_r = s[3] + b_hh[j];
        const float h_z = s[4] + b_hh[j + H];
        const float h_n = s[5] + b_hh[j + 2 * H];
        const float r = 1.f / (1.f + __expf(-(i_r + h_r)));
        const float z = 1.f / (1.f + __expf(-(i_z + h_z)));
        const float n = tanhf(i_n + r * h_n);
        const float hj = ((const float*)hv4)[j];
        const float val = (1.f - z) * n + z * hj;
        g_concat[H + j] = val;
        out_h[j]        = val;
    }
    __threadfence();
    __syncthreads();
    if (tid == 0) { atomicAdd(&g_syncA, 1); spin_until(&g_syncA, NPART); }
    __syncthreads();
    __threadfence();

    // ---------------- phase 1: scores for rows l0..l0+7, enc held in registers -------
    sv[tid] = ((const float4*)g_concat)[256 + tid];   // h_new
    __syncthreads();
    const float4 hsh = sv[tid];
    const int l0 = b * 8;
    const float4* e4 = (const float4*)enc;
    float4 rv[8];
    float p[8];
#pragma unroll
    for (int l = 0; l < 8; l++) {
        rv[l] = e4[(size_t)(l0 + l) * 256 + tid];
        p[l] = dot4(rv[l], hsh);
    }
#pragma unroll
    for (int l = 0; l < 8; l++) {
        p[l] = warp_sum(p[l]);
        if (lane == 0) red[l][warp] = p[l];
    }
    __syncthreads();
    if (tid < 8) {
        float t = red[tid][0];
#pragma unroll
        for (int k = 1; k < 8; k++) t += red[tid][k];
        sarr[tid] = t;
    }
    __syncthreads();
    if (tid == 0) {
        float m = sarr[0];
#pragma unroll
        for (int k = 1; k < 8; k++) m = fmaxf(m, sarr[k]);
        float s = 0.f;
#pragma unroll
        for (int k = 0; k < 8; k++) s += __expf(sarr[k] - m);
        g_spart[2 * b]     = m;
        g_spart[2 * b + 1] = s;
    }
    __threadfence();
    __syncthreads();
    if (tid == 0) { atomicAdd(&g_syncB, 1); spin_until(&g_syncB, NPART); }
    __syncthreads();
    __threadfence();

    // ---------------- phase 2: merge softmax partials, weighted ctx from registers ----
    {
        float m = g_spart[2 * tid], s = g_spart[2 * tid + 1];
        const float m2 = g_spart[2 * (tid + 256)], s2 = g_spart[2 * (tid + 256) + 1];
        const float nm0 = fmaxf(m, m2);
        s = s * __expf(m - nm0) + s2 * __expf(m2 - nm0);
        m = nm0;
#pragma unroll
        for (int o = 16; o > 0; o >>= 1) {
            const float om = __shfl_down_sync(0xFFFFFFFFu, m, o);
            const float os = __shfl_down_sync(0xFFFFFFFFu, s, o);
            const float nm = fmaxf(m, om);
            s = s * __expf(m - nm) + os * __expf(om - nm);
            m = nm;
        }
        if (lane == 0) { red[0][warp] = m; red[1][warp] = s; }
    }
    __syncthreads();
    if (tid < 8) {
        float M = red[0][0], S = red[1][0];
#pragma unroll
        for (int k = 1; k < 8; k++) {
            const float nm = fmaxf(M, red[0][k]);
            S = S * __expf(M - nm) + red[1][k] * __expf(red[0][k] - nm);
            M = nm;
        }
        wts[tid] = __expf(sarr[tid] - M) / S;
    }
    __syncthreads();
    float4 acc = make_float4(0.f, 0.f, 0.f, 0.f);
#pragma unroll
    for (int l = 0; l < 8; l++) {
        const float w = wts[l];
        acc.x += w * rv[l].x; acc.y += w * rv[l].y;
        acc.z += w * rv[l].z; acc.w += w * rv[l].w;
    }
    g_ctx_part4[b * 256 + tid] = acc;
    __threadfence();
    __syncthreads();
    if (tid == 0) atomicAdd(&g_syncC, 1);

    // ---------------- phase 3: blocks 0..63 reduce the L2-hot partials ----------------
    if (b < NRED) {
        if (tid == 0) spin_until(&g_syncC, NPART);
        __syncthreads();
        __threadfence();
        __shared__ float4 sred[256];
        const int c4 = tid & 3;
        const int pg = tid >> 2;
        float4 racc = make_float4(0.f, 0.f, 0.f, 0.f);
#pragma unroll
        for (int k = 0; k < NPART / 64; k++) {
            const float4 v = g_ctx_part4[(pg + 64 * k) * 256 + b * 4 + c4];
            racc.x += v.x; racc.y += v.y; racc.z += v.z; racc.w += v.w;
        }
        sred[tid] = racc;
        __syncthreads();
#pragma unroll
        for (int off = 32; off >= 1; off >>= 1) {
            if (pg < off) {
                const float4 v = sred[tid + off * 4];
                float4 t = sred[tid];
                t.x += v.x; t.y += v.y; t.z += v.z; t.w += v.w;
                sred[tid] = t;
            }
            __syncthreads();
        }
        if (pg == 0) ((float4*)g_concat)[b * 4 + c4] = sred[tid];
    }
}

// ============ 2) logits: block-per-tile float4 matvec (R7 shape, 83.9% DRAM) ============
__global__ void __launch_bounds__(512) logits_kernel(
    const float* __restrict__ out_w, const float* __restrict__ out_b,
    float* __restrict__ logits)
{
    __shared__ float4 cs[512];          // concat (2048 floats) as float4
    const int tid = threadIdx.x;
    const float4* cc = (const float4*)g_concat;
    cs[tid] = cc[tid];
    __syncthreads();
    const int warp = tid >> 5, lane = tid & 31;
    const int row = blockIdx.x * 16 + warp;
    if (row >= V) return;
    const float4* wr = (const float4*)(out_w + (size_t)row * (2 * H));
    float acc = 0.f;
#pragma unroll
    for (int i = 0; i < 16; i++) {
        const float4 w4 = __ldcs(&wr[lane + 32 * i]);   // streaming: don't pollute L2
        const float4 c4 = cs[lane + 32 * i];
        acc += w4.x * c4.x + w4.y * c4.y + w4.z * c4.z + w4.w * c4.w;
    }
    acc = warp_sum(acc);
    if (lane == 0) logits[row] = acc + out_b[row];
}

// ============ 3) finalize: per-block LSE partial + spin + redundant merge + subtract ====
__global__ void __launch_bounds__(256) finalize_kernel(float* __restrict__ logits)
{
    __shared__ float sm[8], ss[8];
    __shared__ float lse_s;
    const int tid = threadIdx.x;
    const int warp = tid >> 5, lane = tid & 31;
    const int v = blockIdx.x * 256 + tid;
    const float lg = (v < V) ? logits[v] : NEG_BIG;

    if (blockIdx.x == 0 && tid == 0) { g_syncA = 0; g_syncB = 0; g_syncC = 0; }  // reset for next replay

    // block-local (max, sumexp)
    float m = lg;
#pragma unroll
    for (int o = 16; o > 0; o >>= 1) m = fmaxf(m, __shfl_down_sync(0xFFFFFFFFu, m, o));
    if (lane == 0) sm[warp] = m;
    __syncthreads();
    if (tid == 0) {
        float t = sm[0];
#pragma unroll
        for (int k = 1; k < 8; k++) t = fmaxf(t, sm[k]);
        lse_s = t;   // broadcast of block max
    }
    __syncthreads();
    const float bm = lse_s;
    float s = (v < V) ? __expf(lg - bm) : 0.f;
    s = warp_sum(s);
    if (lane == 0) ss[warp] = s;
    __syncthreads();
    if (tid == 0) {
        float t = ss[0];
#pragma unroll
        for (int k = 1; k < 8; k++) t += ss[k];
        g_part[2 * blockIdx.x]     = bm;
        g_part[2 * blockIdx.x + 1] = t;
        __threadfence();
        atomicAdd(&g_lse_done, 1);
        while (atomicAdd(&g_lse_done, 0) < FIN_BLOCKS) { }
    }
    __syncthreads();
    __threadfence();

    // redundant merge of all 197 pairs (L2-hot, fixed order -> deterministic)
    float mm = NEG_BIG, msum = 0.f;
    if (tid < FIN_BLOCKS) { mm = g_part[2 * tid]; msum = g_part[2 * tid + 1]; }
#pragma unroll
    for (int o = 16; o > 0; o >>= 1) {
        const float om = __shfl_down_sync(0xFFFFFFFFu, mm, o);
        const float os = __shfl_down_sync(0xFFFFFFFFu, msum, o);
        const float nm = fmaxf(mm, om);
        msum = msum * __expf(mm - nm) + os * __expf(om - nm);
        mm = nm;
    }
    if (lane == 0) { sm[warp] = mm; ss[warp] = msum; }
    __syncthreads();
    if (tid == 0) {
        float M = sm[0], S = ss[0];
#pragma unroll
        for (int k = 1; k < 8; k++) {
            const float nm = fmaxf(M, sm[k]);
            S = S * __expf(M - nm) + ss[k] * __expf(sm[k] - nm);
            M = nm;
        }
        lse_s = M + logf(S);
    }
    __syncthreads();
    if (v < V) logits[v] = lg - lse_s;
}

// ---------------- launcher ----------------
extern "C" void kernel_launch(void* const* d_in, const int* in_sizes, int n_in,
                              void* d_out, int out_size)
{
    const int*   inp   = (const int*)  d_in[0];   // token id (read low 32 bits)
    const float* hidden= (const float*)d_in[1];
    const float* enc   = (const float*)d_in[2];
    const float* emb   = (const float*)d_in[3];
    const float* w_ih  = (const float*)d_in[4];
    const float* w_hh  = (const float*)d_in[5];
    const float* b_ih  = (const float*)d_in[6];
    const float* b_hh  = (const float*)d_in[7];
    const float* out_w = (const float*)d_in[8];
    const float* out_b = (const float*)d_in[9];
    float* out = (float*)d_out;                   // [0..V) log-probs, [V..V+H) h_new

    fused_attn_kernel<<<NPART, 256>>>(inp, hidden, emb, w_ih, w_hh, b_ih, b_hh,
                                      enc, out + V);
    logits_kernel<<<(V + 15) / 16, 512>>>(out_w, out_b, out);
    finalize_kernel<<<FIN_BLOCKS, 256>>>(out);
}